// round 16
// baseline (speedup 1.0000x reference)
#include <cuda_runtime.h>
#include <math.h>
#include <stdint.h>

// ---------------------------------------------------------------------------
// CNN-LSTM: emb-gather -> conv1d(K=5,VALID) -> relu -> maxpool(4) -> LSTM -> FC
// B=64 L=4096 VOCAB=20000 E=128 F=64 K=5 P=4 H=128 C=2
//
//   K0: transpose conv_w -> [e][k*64+f]
//   K1: proj[v][k][f] = emb[v] . conv_w[f,:,k]   (20000x320 table, L2-resident)
//   K2: conv+relu+pool via 20 L2-hit gathers per pooled output
//   K3: xg = pooled @ w_ih^T + biases   (R11 design: best measured, 146us)
//   K4: cluster LSTM v2: 2 CTAs/batch, ALL weights in registers (zero smem
//       weight traffic), local-half GEMV BEFORE the peer wait so the DSMEM
//       flight (~215cyc) is hidden, ping-pong h buffers, 1 bar + 1 wait/step
// ---------------------------------------------------------------------------

using u64 = unsigned long long;
#define DI __device__ __forceinline__

namespace {
constexpr int B_ = 64, L_ = 4096, E_ = 128, F_ = 64, K_ = 5, H_ = 128;
constexpr int VOCAB_ = 20000;
constexpr int FK_ = K_ * F_;     // 320
constexpr int LP_ = 1023;        // pooled sequence length (4092/4)
constexpr int G_ = 4 * H_;       // 512 gate rows
constexpr int M_ = B_ * LP_;     // 65472 pooled rows
}

// scratch (device globals -- no runtime allocation allowed)
__device__ float g_cwt[E_ * FK_];        // transposed conv weights
__device__ float g_proj[VOCAB_ * FK_];   // 25.6 MB token->conv projection table
__device__ float g_pooled[M_ * F_];      // 16.8 MB pooled features
__device__ float g_xg[M_ * G_];          // 134 MB precomputed gate inputs

// ---- packed f32x2 helpers (Blackwell FFMA2) -------------------------------
DI void fma2(u64 &acc, u64 a, u64 b) {
    asm("fma.rn.f32x2 %0, %1, %2, %0;" : "+l"(acc) : "l"(a), "l"(b));
}
DI u64 pk2(float lo, float hi) {
    u64 r;
    asm("mov.b64 %0, {%1, %2};" : "=l"(r) : "f"(lo), "f"(hi));
    return r;
}
DI float sum2(u64 v) {
    float lo, hi;
    asm("mov.b64 {%0, %1}, %2;" : "=f"(lo), "=f"(hi) : "l"(v));
    return lo + hi;
}

DI float sigf(float x) { return 1.0f / (1.0f + __expf(-x)); }

// ---- cluster / mbarrier asm helpers ---------------------------------------
DI uint32_t smem_u32(const void* p) {
    uint32_t a;
    asm("{.reg .u64 t; cvta.to.shared.u64 t, %1; cvt.u32.u64 %0, t;}"
        : "=r"(a) : "l"(p));
    return a;
}
DI uint32_t mapa_u32(uint32_t addr, uint32_t rank) {
    uint32_t d;
    asm("mapa.shared::cluster.u32 %0, %1, %2;" : "=r"(d) : "r"(addr), "r"(rank));
    return d;
}
DI void st_cluster_f32(uint32_t addr, float v) {
    asm volatile("st.shared::cluster.f32 [%0], %1;" :: "r"(addr), "f"(v) : "memory");
}
DI void mbar_init(uint32_t addr, uint32_t cnt) {
    asm volatile("mbarrier.init.shared.b64 [%0], %1;" :: "r"(addr), "r"(cnt) : "memory");
}
DI void mbar_arrive_cluster(uint32_t remote_addr) {
    asm volatile("mbarrier.arrive.release.cluster.shared::cluster.b64 _, [%0];"
                 :: "r"(remote_addr) : "memory");
}
DI void mbar_wait_parity_cluster(uint32_t addr, uint32_t parity) {
    asm volatile(
        "{\n\t"
        ".reg .pred P;\n\t"
        "W_%=:\n\t"
        "mbarrier.try_wait.parity.acquire.cluster.shared::cta.b64 P, [%0], %1, 0x989680;\n\t"
        "@P bra D_%=;\n\t"
        "bra W_%=;\n\t"
        "D_%=:\n\t"
        "}"
        :: "r"(addr), "r"(parity) : "memory");
}
DI void cluster_sync_() {
    asm volatile("barrier.cluster.arrive.aligned;" ::: "memory");
    asm volatile("barrier.cluster.wait.aligned;" ::: "memory");
}

// ---- K0: transpose conv_w [F,E,K] -> g_cwt[e][k*64+f] ---------------------
__global__ void k_wt(const float* __restrict__ cw) {
    int i = blockIdx.x * 256 + threadIdx.x;
    if (i < E_ * FK_) {
        int e = i / FK_, col = i % FK_;
        int k = col >> 6, f = col & 63;
        g_cwt[i] = cw[(f * E_ + e) * K_ + k];
    }
}

// ---- K1: proj table GEMM. CTA = 32 vocab rows staged in smem --------------
__global__ void __launch_bounds__(320) k_proj(const float* __restrict__ emb) {
    __shared__ __align__(16) float es[32 * E_];   // 16 KB
    int c = threadIdx.x;
    u64 w[64];
#pragma unroll
    for (int j = 0; j < 64; j++)
        w[j] = pk2(g_cwt[(2 * j) * FK_ + c], g_cwt[(2 * j + 1) * FK_ + c]);
    int v0 = blockIdx.x * 32;
    const float4* src = (const float4*)(emb + v0 * E_);
    for (int i = threadIdx.x; i < 32 * E_ / 4; i += 320)
        ((float4*)es)[i] = src[i];
    __syncthreads();
#pragma unroll 1
    for (int vi = 0; vi < 32; vi++) {
        const ulonglong2* h4 = (const ulonglong2*)(es + vi * E_);
        u64 a0 = 0ull, a1 = 0ull;
#pragma unroll
        for (int j = 0; j < 32; j++) {
            ulonglong2 h = h4[j];
            fma2(a0, h.x, w[2 * j]);
            fma2(a1, h.y, w[2 * j + 1]);
        }
        g_proj[(v0 + vi) * FK_ + c] = sum2(a0) + sum2(a1);
    }
}

// ---- K2: conv + relu + maxpool. thread = (b, pooled pos p, feature f) -----
__global__ void k_convpool(const int* __restrict__ x, const float* __restrict__ cb) {
    int f = threadIdx.x & 63;
    int p = blockIdx.x * 4 + (threadIdx.x >> 6);
    int b = blockIdx.y;
    if (p >= LP_) return;
    const int* xb = x + b * L_;
    int s0 = p * 4;
    int tok[8];
#pragma unroll
    for (int i = 0; i < 8; i++) tok[i] = __ldg(xb + s0 + i);
    float a0 = 0.f, a1 = 0.f, a2 = 0.f, a3 = 0.f;
#pragma unroll
    for (int k = 0; k < K_; k++) {
        const float* pr = g_proj + k * 64 + f;
        a0 += __ldg(pr + tok[k + 0] * FK_);
        a1 += __ldg(pr + tok[k + 1] * FK_);
        a2 += __ldg(pr + tok[k + 2] * FK_);
        a3 += __ldg(pr + tok[k + 3] * FK_);
    }
    float bias = __ldg(cb + f);
    float m = fmaxf(fmaxf(a0, a1), fmaxf(a2, a3)) + bias;
    g_pooled[(b * LP_ + p) * F_ + f] = fmaxf(m, 0.0f);  // relu(max) == max(relu)
}

// ---- K3: xg = pooled @ w_ih^T + (b_ih + b_hh)  [R11 design: best measured] -
// CTA = 256 threads covering ALL 512 gate cols (2 cols/thread: t and t+256),
// 64 pooled rows staged in smem. Each LDS.128 broadcast feeds 4 FFMA2.
__global__ void __launch_bounds__(256) k_xgate(const float* __restrict__ wih,
                                               const float* __restrict__ bih,
                                               const float* __restrict__ bhh) {
    __shared__ __align__(16) float ps[64 * F_];   // 16 KB
    int t = threadIdx.x;
    u64 w0[32], w1[32];
    const u64* wr0 = (const u64*)(wih + t * F_);
    const u64* wr1 = (const u64*)(wih + (t + 256) * F_);
#pragma unroll
    for (int j = 0; j < 32; j++) { w0[j] = wr0[j]; w1[j] = wr1[j]; }
    float b0 = __ldg(bih + t) + __ldg(bhh + t);
    float b1 = __ldg(bih + t + 256) + __ldg(bhh + t + 256);
    int row0 = blockIdx.x * 64;
    const float4* src = (const float4*)(g_pooled + row0 * F_);
#pragma unroll
    for (int i = 0; i < 4; i++) ((float4*)ps)[t + i * 256] = src[t + i * 256];
    __syncthreads();
#pragma unroll 1
    for (int r = 0; r < 64; r += 4) {
        const ulonglong2* p0 = (const ulonglong2*)(ps + (r + 0) * F_);
        const ulonglong2* p1 = (const ulonglong2*)(ps + (r + 1) * F_);
        const ulonglong2* p2 = (const ulonglong2*)(ps + (r + 2) * F_);
        const ulonglong2* p3 = (const ulonglong2*)(ps + (r + 3) * F_);
        u64 a0A = 0ull, a1A = 0ull, a2A = 0ull, a3A = 0ull;
        u64 a0B = 0ull, a1B = 0ull, a2B = 0ull, a3B = 0ull;
#pragma unroll
        for (int j = 0; j < 16; j++) {
            u64 wl0 = w0[2 * j], wh0 = w0[2 * j + 1];
            u64 wl1 = w1[2 * j], wh1 = w1[2 * j + 1];
            ulonglong2 h0 = p0[j], h1 = p1[j], h2 = p2[j], h3 = p3[j];
            fma2(a0A, h0.x, wl0); fma2(a0A, h0.y, wh0);
            fma2(a0B, h0.x, wl1); fma2(a0B, h0.y, wh1);
            fma2(a1A, h1.x, wl0); fma2(a1A, h1.y, wh0);
            fma2(a1B, h1.x, wl1); fma2(a1B, h1.y, wh1);
            fma2(a2A, h2.x, wl0); fma2(a2A, h2.y, wh0);
            fma2(a2B, h2.x, wl1); fma2(a2B, h2.y, wh1);
            fma2(a3A, h3.x, wl0); fma2(a3A, h3.y, wh0);
            fma2(a3B, h3.x, wl1); fma2(a3B, h3.y, wh1);
        }
        float* dst = g_xg + (size_t)(row0 + r) * G_ + t;
        dst[0 * G_]       = sum2(a0A) + b0;
        dst[0 * G_ + 256] = sum2(a0B) + b1;
        dst[1 * G_]       = sum2(a1A) + b0;
        dst[1 * G_ + 256] = sum2(a1B) + b1;
        dst[2 * G_]       = sum2(a2A) + b0;
        dst[2 * G_ + 256] = sum2(a2B) + b1;
        dst[3 * G_]       = sum2(a3A) + b0;
        dst[3 * G_ + 256] = sum2(a3B) + b1;
    }
}

// ---- K4: cluster LSTM v2. 2 CTAs/batch, 256 threads each. -----------------
// CTA rank r owns global elements eg in [r*64, r*64+64). Thread layout: warp
// w, lane l; local element el = w*8 + (l>>2); gate = l&3 (i,f,g,o in adjacent
// lanes -> 3 shuffles combine); row = gate*128 + r*64 + el. The FULL 128-wide
// weight row lives in 64 u64 registers -> NO smem weight traffic.
// Per step: [local-half GEMV over own 64 h values] -> [wait peer mbar, phase
// p-1] -> [peer-half GEMV] -> activations -> writers store h locally + DSMEM
// to peer buf[p&1] + arrive(release) on peer mbar -> __syncthreads.
// The peer's DSMEM stores fly during our barrier+local GEMV, hiding latency.
// Ping-pong h buffers make step-p writes disjoint from step-p reads.
__global__ void __launch_bounds__(256, 1) __cluster_dims__(2, 1, 1)
k_lstm(const float* __restrict__ whh, const float* __restrict__ fcw,
       const float* __restrict__ fcb, float* __restrict__ out) {
    __shared__ __align__(16) float hbuf[2][H_];
    __shared__ __align__(8) u64 mbar[1];

    int t = threadIdx.x;
    uint32_t rank;
    asm("mov.u32 %0, %%cluster_ctarank;" : "=r"(rank));
    int b = blockIdx.x >> 1;
    int l = t & 31;
    int el = (t >> 5) * 8 + (l >> 2);          // local element 0..63
    int gate = l & 3;                          // 0=i 1=f 2=g 3=o
    int eg = (int)rank * 64 + el;              // global element 0..127
    int row = gate * H_ + eg;
    bool writer = (gate == 0);

    // full 128-wide weight row in registers
    u64 wr_[64];
    const u64* wp = (const u64*)(whh + (size_t)row * H_);
#pragma unroll
    for (int j = 0; j < 64; j++) wr_[j] = wp[j];

    if (t < 128) { hbuf[0][t] = 0.0f; hbuf[1][t] = 0.0f; }
    uint32_t mb = smem_u32(mbar);
    if (t == 0) mbar_init(mb, 64);
    __syncthreads();
    cluster_sync_();   // mbar init + zeroed h visible before any remote traffic

    uint32_t peer = rank ^ 1u;
    uint32_t r_h0 = mapa_u32(smem_u32(&hbuf[0][eg]), peer);
    uint32_t r_h1 = mapa_u32(smem_u32(&hbuf[1][eg]), peer);
    uint32_t r_mb = mapa_u32(mb, peer);

    const int LOC = (int)rank * 16;    // local-half ulonglong2 offset in hbuf
    const int LW  = (int)rank * 32;    // local-half weight u64 offset
    const int PEO = 16 - LOC;          // peer-half offsets
    const int PW  = 32 - LW;

    const float* xgb = g_xg + (size_t)b * (LP_ * G_) + row;
    float x0 = __ldg(xgb);
    float x1 = __ldg(xgb + G_);
    float c = 0.0f;

#pragma unroll 1
    for (int p = 0; p < LP_; p++) {
        int pn = (p + 2 < LP_) ? p + 2 : LP_ - 1;
        float x2 = __ldg(xgb + (size_t)pn * G_);

        const ulonglong2* hprev = (const ulonglong2*)hbuf[(p & 1) ^ 1];

        // ---- local-half GEMV (own 64 h values; ready since last barrier)
        u64 a0 = 0ull, a1 = 0ull, a2 = 0ull, a3 = 0ull;
#pragma unroll
        for (int j = 0; j < 16; j += 2) {
            ulonglong2 h0 = hprev[LOC + j], h1 = hprev[LOC + j + 1];
            fma2(a0, h0.x, wr_[LW + 2 * j]);
            fma2(a1, h0.y, wr_[LW + 2 * j + 1]);
            fma2(a2, h1.x, wr_[LW + 2 * j + 2]);
            fma2(a3, h1.y, wr_[LW + 2 * j + 3]);
        }

        // ---- wait for peer's h half of step p-1 (DSMEM store has been
        //      in flight during our barrier + local GEMV)
        if (p > 0) mbar_wait_parity_cluster(mb, (uint32_t)((p - 1) & 1));

        // ---- peer-half GEMV
#pragma unroll
        for (int j = 0; j < 16; j += 2) {
            ulonglong2 h0 = hprev[PEO + j], h1 = hprev[PEO + j + 1];
            fma2(a0, h0.x, wr_[PW + 2 * j]);
            fma2(a1, h0.y, wr_[PW + 2 * j + 1]);
            fma2(a2, h1.x, wr_[PW + 2 * j + 2]);
            fma2(a3, h1.y, wr_[PW + 2 * j + 3]);
        }
        float pre = (sum2(a0) + sum2(a1)) + (sum2(a2) + sum2(a3)) + x0;
        x0 = x1; x1 = x2;

        // sigmoid for i,f,o; tanh for g (= 2*sig(2x)-1)
        float q   = (gate == 2) ? (pre + pre) : pre;
        float s   = sigf(q);
        float act = (gate == 2) ? (2.0f * s - 1.0f) : s;

        // quad gather onto gate-0 lane: +1=f, +2=g, +3=o
        float vf = __shfl_down_sync(0xffffffffu, act, 1);
        float vg = __shfl_down_sync(0xffffffffu, act, 2);
        float vo = __shfl_down_sync(0xffffffffu, act, 3);

        if (writer) {
            c = vf * c + act * vg;
            float tc = 2.0f * sigf(c + c) - 1.0f;    // tanh(c)
            float h = vo * tc;
            hbuf[p & 1][eg] = h;                     // local copy
            st_cluster_f32((p & 1) ? r_h1 : r_h0, h);// peer copy (in flight)
            mbar_arrive_cluster(r_mb);               // release my store
        }
        __syncthreads();   // local h half visible for next step's local GEMV
    }

    // final h is in hbuf[0] (LP_-1 = 1022 even); wait for peer's final half
    mbar_wait_parity_cluster(mb, (uint32_t)((LP_ - 1) & 1));

    if (rank == 0 && t < 64) {
        int cc = t >> 5, lane = t & 31;
        float s = 0.0f;
#pragma unroll
        for (int u = 0; u < 4; u++)
            s += hbuf[0][lane + u * 32] * __ldg(fcw + cc * H_ + lane + u * 32);
#pragma unroll
        for (int off = 16; off; off >>= 1) s += __shfl_down_sync(0xffffffffu, s, off);
        if (lane == 0) out[b * 2 + cc] = s + __ldg(fcb + cc);
    }
    // keep both CTAs alive until all remote traffic has landed
    cluster_sync_();
}

// ---------------------------------------------------------------------------
extern "C" void kernel_launch(void* const* d_in, const int* in_sizes, int n_in,
                              void* d_out, int out_size) {
    const int*   x   = (const int*)d_in[0];
    const float* emb = (const float*)d_in[1];
    const float* cw  = (const float*)d_in[2];
    const float* cb  = (const float*)d_in[3];
    const float* wih = (const float*)d_in[4];
    const float* whh = (const float*)d_in[5];
    const float* bih = (const float*)d_in[6];
    const float* bhh = (const float*)d_in[7];
    const float* fcw = (const float*)d_in[8];
    const float* fcb = (const float*)d_in[9];
    float* out = (float*)d_out;

    k_wt<<<(E_ * FK_ + 255) / 256, 256>>>(cw);
    k_proj<<<VOCAB_ / 32, 320>>>(emb);
    k_convpool<<<dim3((LP_ + 3) / 4, B_), 256>>>(x, cb);
    k_xgate<<<M_ / 64, 256>>>(wih, bih, bhh);
    k_lstm<<<2 * B_, 256>>>(whh, fcw, fcb, out);
}

// round 17
// speedup vs baseline: 2.0687x; 2.0687x over previous
#include <cuda_runtime.h>
#include <math.h>
#include <stdint.h>

// ---------------------------------------------------------------------------
// CNN-LSTM: emb-gather -> conv1d(K=5,VALID) -> relu -> maxpool(4) -> LSTM -> FC
// B=64 L=4096 VOCAB=20000 E=128 F=64 K=5 P=4 H=128 C=2
//
//   K0: transpose conv_w -> [e][k*64+f]
//   K1: proj[v][k][f] = emb[v] . conv_w[f,:,k]   (20000x320 table, L2-resident)
//   K2: conv+relu+pool via 20 L2-hit gathers per pooled output
//   K3: xg = pooled @ w_ih^T + biases   (R11 design: best measured, 146us x3)
//   K4: persistent LSTM, 1 CTA/batch, 256 threads (best measured class),
//       shuffle-paired gates, ping-pong h buffers, ONE barrier/step,
//       2-step xg prefetch, software-prefetched smem weight loads
// ---------------------------------------------------------------------------

using u64 = unsigned long long;
#define DI __device__ __forceinline__

namespace {
constexpr int B_ = 64, L_ = 4096, E_ = 128, F_ = 64, K_ = 5, H_ = 128;
constexpr int VOCAB_ = 20000;
constexpr int FK_ = K_ * F_;     // 320
constexpr int LP_ = 1023;        // pooled sequence length (4092/4)
constexpr int G_ = 4 * H_;       // 512 gate rows
constexpr int M_ = B_ * LP_;     // 65472 pooled rows
}

// scratch (device globals -- no runtime allocation allowed)
__device__ float g_cwt[E_ * FK_];        // transposed conv weights
__device__ float g_proj[VOCAB_ * FK_];   // 25.6 MB token->conv projection table
__device__ float g_pooled[M_ * F_];      // 16.8 MB pooled features
__device__ float g_xg[M_ * G_];          // 134 MB precomputed gate inputs

// ---- packed f32x2 helpers (Blackwell FFMA2) -------------------------------
DI void fma2(u64 &acc, u64 a, u64 b) {
    asm("fma.rn.f32x2 %0, %1, %2, %0;" : "+l"(acc) : "l"(a), "l"(b));
}
DI u64 pk2(float lo, float hi) {
    u64 r;
    asm("mov.b64 %0, {%1, %2};" : "=l"(r) : "f"(lo), "f"(hi));
    return r;
}
DI float sum2(u64 v) {
    float lo, hi;
    asm("mov.b64 {%0, %1}, %2;" : "=f"(lo), "=f"(hi) : "l"(v));
    return lo + hi;
}

DI float sigf(float x) { return 1.0f / (1.0f + __expf(-x)); }

// ---- K0: transpose conv_w [F,E,K] -> g_cwt[e][k*64+f] ---------------------
__global__ void k_wt(const float* __restrict__ cw) {
    int i = blockIdx.x * 256 + threadIdx.x;
    if (i < E_ * FK_) {
        int e = i / FK_, col = i % FK_;
        int k = col >> 6, f = col & 63;
        g_cwt[i] = cw[(f * E_ + e) * K_ + k];
    }
}

// ---- K1: proj table GEMM. CTA = 32 vocab rows staged in smem --------------
__global__ void __launch_bounds__(320) k_proj(const float* __restrict__ emb) {
    __shared__ __align__(16) float es[32 * E_];   // 16 KB
    int c = threadIdx.x;
    u64 w[64];
#pragma unroll
    for (int j = 0; j < 64; j++)
        w[j] = pk2(g_cwt[(2 * j) * FK_ + c], g_cwt[(2 * j + 1) * FK_ + c]);
    int v0 = blockIdx.x * 32;
    const float4* src = (const float4*)(emb + v0 * E_);
    for (int i = threadIdx.x; i < 32 * E_ / 4; i += 320)
        ((float4*)es)[i] = src[i];
    __syncthreads();
#pragma unroll 1
    for (int vi = 0; vi < 32; vi++) {
        const ulonglong2* h4 = (const ulonglong2*)(es + vi * E_);
        u64 a0 = 0ull, a1 = 0ull;
#pragma unroll
        for (int j = 0; j < 32; j++) {
            ulonglong2 h = h4[j];
            fma2(a0, h.x, w[2 * j]);
            fma2(a1, h.y, w[2 * j + 1]);
        }
        g_proj[(v0 + vi) * FK_ + c] = sum2(a0) + sum2(a1);
    }
}

// ---- K2: conv + relu + maxpool. thread = (b, pooled pos p, feature f) -----
__global__ void k_convpool(const int* __restrict__ x, const float* __restrict__ cb) {
    int f = threadIdx.x & 63;
    int p = blockIdx.x * 4 + (threadIdx.x >> 6);
    int b = blockIdx.y;
    if (p >= LP_) return;
    const int* xb = x + b * L_;
    int s0 = p * 4;
    int tok[8];
#pragma unroll
    for (int i = 0; i < 8; i++) tok[i] = __ldg(xb + s0 + i);
    float a0 = 0.f, a1 = 0.f, a2 = 0.f, a3 = 0.f;
#pragma unroll
    for (int k = 0; k < K_; k++) {
        const float* pr = g_proj + k * 64 + f;
        a0 += __ldg(pr + tok[k + 0] * FK_);
        a1 += __ldg(pr + tok[k + 1] * FK_);
        a2 += __ldg(pr + tok[k + 2] * FK_);
        a3 += __ldg(pr + tok[k + 3] * FK_);
    }
    float bias = __ldg(cb + f);
    float m = fmaxf(fmaxf(a0, a1), fmaxf(a2, a3)) + bias;
    g_pooled[(b * LP_ + p) * F_ + f] = fmaxf(m, 0.0f);  // relu(max) == max(relu)
}

// ---- K3: xg = pooled @ w_ih^T + (b_ih + b_hh)  [R11 design, 146us x3] -----
// CTA = 256 threads covering ALL 512 gate cols (2 cols/thread: t and t+256),
// 64 pooled rows staged in smem. Each LDS.128 broadcast feeds 4 FFMA2.
__global__ void __launch_bounds__(256) k_xgate(const float* __restrict__ wih,
                                               const float* __restrict__ bih,
                                               const float* __restrict__ bhh) {
    __shared__ __align__(16) float ps[64 * F_];   // 16 KB
    int t = threadIdx.x;
    u64 w0[32], w1[32];
    const u64* wr0 = (const u64*)(wih + t * F_);
    const u64* wr1 = (const u64*)(wih + (t + 256) * F_);
#pragma unroll
    for (int j = 0; j < 32; j++) { w0[j] = wr0[j]; w1[j] = wr1[j]; }
    float b0 = __ldg(bih + t) + __ldg(bhh + t);
    float b1 = __ldg(bih + t + 256) + __ldg(bhh + t + 256);
    int row0 = blockIdx.x * 64;
    const float4* src = (const float4*)(g_pooled + row0 * F_);
#pragma unroll
    for (int i = 0; i < 4; i++) ((float4*)ps)[t + i * 256] = src[t + i * 256];
    __syncthreads();
#pragma unroll 1
    for (int r = 0; r < 64; r += 4) {
        const ulonglong2* p0 = (const ulonglong2*)(ps + (r + 0) * F_);
        const ulonglong2* p1 = (const ulonglong2*)(ps + (r + 1) * F_);
        const ulonglong2* p2 = (const ulonglong2*)(ps + (r + 2) * F_);
        const ulonglong2* p3 = (const ulonglong2*)(ps + (r + 3) * F_);
        u64 a0A = 0ull, a1A = 0ull, a2A = 0ull, a3A = 0ull;
        u64 a0B = 0ull, a1B = 0ull, a2B = 0ull, a3B = 0ull;
#pragma unroll
        for (int j = 0; j < 16; j++) {
            u64 wl0 = w0[2 * j], wh0 = w0[2 * j + 1];
            u64 wl1 = w1[2 * j], wh1 = w1[2 * j + 1];
            ulonglong2 h0 = p0[j], h1 = p1[j], h2 = p2[j], h3 = p3[j];
            fma2(a0A, h0.x, wl0); fma2(a0A, h0.y, wh0);
            fma2(a0B, h0.x, wl1); fma2(a0B, h0.y, wh1);
            fma2(a1A, h1.x, wl0); fma2(a1A, h1.y, wh0);
            fma2(a1B, h1.x, wl1); fma2(a1B, h1.y, wh1);
            fma2(a2A, h2.x, wl0); fma2(a2A, h2.y, wh0);
            fma2(a2B, h2.x, wl1); fma2(a2B, h2.y, wh1);
            fma2(a3A, h3.x, wl0); fma2(a3A, h3.y, wh0);
            fma2(a3B, h3.x, wl1); fma2(a3B, h3.y, wh1);
        }
        float* dst = g_xg + (size_t)(row0 + r) * G_ + t;
        dst[0 * G_]       = sum2(a0A) + b0;
        dst[0 * G_ + 256] = sum2(a0B) + b1;
        dst[1 * G_]       = sum2(a1A) + b0;
        dst[1 * G_ + 256] = sum2(a1B) + b1;
        dst[2 * G_]       = sum2(a2A) + b0;
        dst[2 * G_ + 256] = sum2(a2B) + b1;
        dst[3 * G_]       = sum2(a3A) + b0;
        dst[3 * G_ + 256] = sum2(a3B) + b1;
    }
}

// ---- K4: persistent LSTM. 1 CTA/batch, 256 threads, 2 gate rows/thread ----
// Warp w, lane l. Element e = w*16 + (l&15). Lanes 0-15 ("role A") own gate
// rows (i=e, g=256+e) and the cell state c[e]; lanes 16-31 ("role B") own
// rows (f=128+e, o=384+e). f/o activations hop A<-B via __shfl_down(16).
// h is PING-PONG buffered: step p reads buf[(p-1)&1], writes buf[p&1] ->
// single per-step __syncthreads, race-free.
// Weights: rowA in regs (64 u64), rowB 32 u64 regs + 16 ulonglong2 smem.
// smem weight loads are SOFTWARE-PREFETCHED one unroll-iter ahead so their
// 29-cyc LDS latency overlaps the FFMA2 stream.
__global__ void __launch_bounds__(256, 1) k_lstm(const float* __restrict__ whh,
                                                 const float* __restrict__ fcw,
                                                 const float* __restrict__ fcb,
                                                 float* __restrict__ out) {
    extern __shared__ float sm[];
    ulonglong2* wsm = (ulonglong2*)sm;    // [16][256] ulonglong2 -> 64 KB
    float* hbase = sm + 16384;            // two h buffers of 128 floats each

    int t = threadIdx.x;
    int b = blockIdx.x;
    int l = t & 31;
    bool roleA = (l < 16);
    int e = (t >> 5) * 16 + (l & 15);
    int rowA = roleA ? e : (128 + e);          // i : f
    int rowB = roleA ? (256 + e) : (384 + e);  // g : o

    u64 wa[64], wb[32];
    const u64* rA = (const u64*)(whh + rowA * H_);
    const u64* rB = (const u64*)(whh + rowB * H_);
#pragma unroll
    for (int j = 0; j < 64; j++) wa[j] = rA[j];
#pragma unroll
    for (int j = 0; j < 32; j++) wb[j] = rB[j];
    const ulonglong2* rB2 = (const ulonglong2*)(whh + rowB * H_ + 64);
#pragma unroll
    for (int p2 = 0; p2 < 16; p2++) wsm[p2 * 256 + t] = rB2[p2];
    if (t < 256) hbase[t] = 0.0f;   // zero both h buffers
    float c = 0.0f;
    __syncthreads();

    const float* xgb = g_xg + (size_t)b * (LP_ * G_);
    // 2-deep xg prefetch ring (covers DRAM latency even on fast steps)
    float xa0  = __ldg(xgb + rowA);
    float xb0  = __ldg(xgb + rowB);
    float xa1  = __ldg(xgb + G_ + rowA);
    float xb1  = __ldg(xgb + G_ + rowB);
#pragma unroll 1
    for (int p = 0; p < LP_; p++) {
        int pn = (p + 2 < LP_) ? p + 2 : LP_ - 1;
        float xa2  = __ldg(xgb + (size_t)pn * G_ + rowA);
        float xb2n = __ldg(xgb + (size_t)pn * G_ + rowB);

        // read h_{p-1} from buf[(p-1)&1]  (p=0 -> buf1 = zeros)
        const ulonglong2* h4 =
            (const ulonglong2*)(hbase + (((p & 1) ^ 1) << 7));
        u64 aA0 = 0ull, aA1 = 0ull, aB0 = 0ull, aB1 = 0ull;

        // prime the smem weight pipeline (first pair in flight early)
        ulonglong2 wv0 = wsm[t];            // j=16 weights
        ulonglong2 wv1 = wsm[256 + t];      // j=17 weights

#pragma unroll
        for (int j = 0; j < 16; j += 2) {     // h[0:64): both operands in regs
            ulonglong2 h0 = h4[j], h1 = h4[j + 1];
            fma2(aA0, h0.x, wa[2 * j]);     fma2(aA0, h0.y, wa[2 * j + 1]);
            fma2(aA1, h1.x, wa[2 * j + 2]); fma2(aA1, h1.y, wa[2 * j + 3]);
            fma2(aB0, h0.x, wb[2 * j]);     fma2(aB0, h0.y, wb[2 * j + 1]);
            fma2(aB1, h1.x, wb[2 * j + 2]); fma2(aB1, h1.y, wb[2 * j + 3]);
        }
#pragma unroll
        for (int j = 16; j < 32; j += 2) {    // h[64:128): rowB weights smem
            ulonglong2 h0 = h4[j], h1 = h4[j + 1];
            // prefetch next iteration's weight pair while using current one
            ulonglong2 nv0, nv1;
            if (j < 30) {
                nv0 = wsm[(j - 14) * 256 + t];
                nv1 = wsm[(j - 13) * 256 + t];
            }
            fma2(aA0, h0.x, wa[2 * j]);     fma2(aA0, h0.y, wa[2 * j + 1]);
            fma2(aA1, h1.x, wa[2 * j + 2]); fma2(aA1, h1.y, wa[2 * j + 3]);
            fma2(aB0, h0.x, wv0.x);         fma2(aB0, h0.y, wv0.y);
            fma2(aB1, h1.x, wv1.x);         fma2(aB1, h1.y, wv1.y);
            if (j < 30) { wv0 = nv0; wv1 = nv1; }
        }
        float pA = sum2(aA0) + sum2(aA1) + xa0;   // i-pre (A) / f-pre (B)
        float pB = sum2(aB0) + sum2(aB1) + xb0;   // g-pre (A) / o-pre (B)
        xa0 = xa1; xb0 = xb1; xa1 = xa2; xb1 = xb2n;

        float sA = sigf(pA);                       // ii (A) / ff (B)
        float q  = roleA ? (pB + pB) : pB;         // tanh(x)=2*sig(2x)-1
        float sq = sigf(q);
        float vB = roleA ? (2.0f * sq - 1.0f) : sq;  // tg (A) / oo (B)

        float ff = __shfl_down_sync(0xffffffffu, sA, 16);
        float oo = __shfl_down_sync(0xffffffffu, vB, 16);
        if (roleA) {
            c = ff * c + sA * vB;
            float tc = 2.0f * sigf(c + c) - 1.0f;  // tanh(c)
            hbase[((p & 1) << 7) + e] = oo * tc;   // write buf[p&1]
        }
        __syncthreads();
    }

    // final h lives in buf[(LP_-1)&1] == buf0 (1022 is even)
    if (t < 64) {
        int cc = t >> 5, lane = t & 31;
        float s = 0.0f;
#pragma unroll
        for (int u = 0; u < 4; u++)
            s += hbase[lane + u * 32] * __ldg(fcw + cc * H_ + lane + u * 32);
#pragma unroll
        for (int off = 16; off; off >>= 1) s += __shfl_down_sync(0xffffffffu, s, off);
        if (lane == 0) out[b * 2 + cc] = s + __ldg(fcb + cc);
    }
}

// ---------------------------------------------------------------------------
extern "C" void kernel_launch(void* const* d_in, const int* in_sizes, int n_in,
                              void* d_out, int out_size) {
    const int*   x   = (const int*)d_in[0];
    const float* emb = (const float*)d_in[1];
    const float* cw  = (const float*)d_in[2];
    const float* cb  = (const float*)d_in[3];
    const float* wih = (const float*)d_in[4];
    const float* whh = (const float*)d_in[5];
    const float* bih = (const float*)d_in[6];
    const float* bhh = (const float*)d_in[7];
    const float* fcw = (const float*)d_in[8];
    const float* fcb = (const float*)d_in[9];
    float* out = (float*)d_out;

    const int lstm_smem = 65536 + 256 * 4;   // weights (64KB) + 2 h buffers
    cudaFuncSetAttribute(k_lstm, cudaFuncAttributeMaxDynamicSharedMemorySize,
                         lstm_smem);

    k_wt<<<(E_ * FK_ + 255) / 256, 256>>>(cw);
    k_proj<<<VOCAB_ / 32, 320>>>(emb);
    k_convpool<<<dim3((LP_ + 3) / 4, B_), 256>>>(x, cb);
    k_xgate<<<M_ / 64, 256>>>(wih, bih, bhh);
    k_lstm<<<B_, 256, lstm_smem>>>(whh, fcw, fcb, out);
}